// round 2
// baseline (speedup 1.0000x reference)
#include <cuda_runtime.h>

// SpikeLoss: delta = outputs - psp(target, tau_s=5); loss = 0.5 * sum(delta^2)
// psp: syn_t = syn_{t-1} * (1 - 1/tau) + x_t ; y_t = syn_t / tau   (scan over
// the LAST, contiguous axis, T=100).
//
// Layout: [B,C,H,W,T] row-major => rows of T=100 contiguous floats.
// One thread per row; float4 streaming loads (25 per tensor per row);
// per-thread partial sum -> warp shfl reduce -> block smem reduce ->
// one atomicAdd per block into the scalar output.

static constexpr int   T_STEPS = 100;
static constexpr int   T_VEC   = T_STEPS / 4;   // 25
static constexpr float TAU_S   = 5.0f;

__global__ void zero_out_kernel(float* __restrict__ out) {
    out[0] = 0.0f;
}

__global__ __launch_bounds__(256)
void spike_loss_kernel(const float* __restrict__ outputs,
                       const float* __restrict__ target,
                       float* __restrict__ out,
                       int n_rows) {
    const int row = blockIdx.x * blockDim.x + threadIdx.x;

    float acc = 0.0f;
    if (row < n_rows) {
        const float4* __restrict__ trow =
            reinterpret_cast<const float4*>(target)  + (size_t)row * T_VEC;
        const float4* __restrict__ orow =
            reinterpret_cast<const float4*>(outputs) + (size_t)row * T_VEC;

        const float decay   = 1.0f - 1.0f / TAU_S;   // 0.8
        const float inv_tau = 1.0f / TAU_S;          // 0.2

        float syn = 0.0f;
        #pragma unroll
        for (int i = 0; i < T_VEC; ++i) {
            const float4 tv = trow[i];
            const float4 ov = orow[i];

            syn = fmaf(syn, decay, tv.x);
            float d = fmaf(-syn, inv_tau, ov.x);
            acc = fmaf(d, d, acc);

            syn = fmaf(syn, decay, tv.y);
            d = fmaf(-syn, inv_tau, ov.y);
            acc = fmaf(d, d, acc);

            syn = fmaf(syn, decay, tv.z);
            d = fmaf(-syn, inv_tau, ov.z);
            acc = fmaf(d, d, acc);

            syn = fmaf(syn, decay, tv.w);
            d = fmaf(-syn, inv_tau, ov.w);
            acc = fmaf(d, d, acc);
        }
    }

    // Warp reduction
    #pragma unroll
    for (int off = 16; off > 0; off >>= 1)
        acc += __shfl_down_sync(0xffffffffu, acc, off);

    __shared__ float warp_sums[8];
    const int lane = threadIdx.x & 31;
    const int wid  = threadIdx.x >> 5;
    if (lane == 0) warp_sums[wid] = acc;
    __syncthreads();

    if (wid == 0) {
        acc = (lane < (blockDim.x >> 5)) ? warp_sums[lane] : 0.0f;
        #pragma unroll
        for (int off = 4; off > 0; off >>= 1)
            acc += __shfl_down_sync(0xffffffffu, acc, off);
        if (lane == 0)
            atomicAdd(out, 0.5f * acc);
    }
}

extern "C" void kernel_launch(void* const* d_in, const int* in_sizes, int n_in,
                              void* d_out, int out_size) {
    const float* outputs = (const float*)d_in[0];
    const float* target  = (const float*)d_in[1];
    float*       out     = (float*)d_out;

    const int n_elems = in_sizes[0];
    const int n_rows  = n_elems / T_STEPS;   // 131072

    zero_out_kernel<<<1, 1>>>(out);

    const int threads = 256;
    const int blocks  = (n_rows + threads - 1) / threads;   // 512
    spike_loss_kernel<<<blocks, threads>>>(outputs, target, out, n_rows);
}